// round 3
// baseline (speedup 1.0000x reference)
#include <cuda_runtime.h>
#include <math.h>

#define B_    8
#define T_    2048
#define DIN   512
#define DA    8
#define DOUT  512

__device__ __align__(16) float g_Q[B_ * T_ * DA];
__device__ __align__(16) float g_K[B_ * T_ * DA];
__device__ __align__(16) float g_V[B_ * T_ * DOUT];

// ---------------------------------------------------------------------------
// Kernel 1: Q,K projections. One warp per 4 tokens (amortize W loads 4x).
// ---------------------------------------------------------------------------
__global__ __launch_bounds__(256) void qk_kernel(const float* __restrict__ X,
                                                 const float* __restrict__ Wq,
                                                 const float* __restrict__ Wk) {
    int warp = threadIdx.x >> 5;
    int lane = threadIdx.x & 31;
    int tok0 = blockIdx.x * 32 + warp * 4;

    float aq[4][8], ak[4][8];
#pragma unroll
    for (int t = 0; t < 4; t++)
#pragma unroll
        for (int f = 0; f < 8; f++) { aq[t][f] = 0.f; ak[t][f] = 0.f; }

#pragma unroll 4
    for (int d = lane; d < DIN; d += 32) {
        float xv[4];
#pragma unroll
        for (int t = 0; t < 4; t++) xv[t] = X[(size_t)(tok0 + t) * DIN + d];
        float4 q0 = *(const float4*)(Wq + (size_t)d * 8);
        float4 q1 = *(const float4*)(Wq + (size_t)d * 8 + 4);
        float4 k0 = *(const float4*)(Wk + (size_t)d * 8);
        float4 k1 = *(const float4*)(Wk + (size_t)d * 8 + 4);
#pragma unroll
        for (int t = 0; t < 4; t++) {
            aq[t][0] += xv[t] * q0.x; aq[t][1] += xv[t] * q0.y;
            aq[t][2] += xv[t] * q0.z; aq[t][3] += xv[t] * q0.w;
            aq[t][4] += xv[t] * q1.x; aq[t][5] += xv[t] * q1.y;
            aq[t][6] += xv[t] * q1.z; aq[t][7] += xv[t] * q1.w;
            ak[t][0] += xv[t] * k0.x; ak[t][1] += xv[t] * k0.y;
            ak[t][2] += xv[t] * k0.z; ak[t][3] += xv[t] * k0.w;
            ak[t][4] += xv[t] * k1.x; ak[t][5] += xv[t] * k1.y;
            ak[t][6] += xv[t] * k1.z; ak[t][7] += xv[t] * k1.w;
        }
    }

#pragma unroll
    for (int t = 0; t < 4; t++) {
#pragma unroll
        for (int f = 0; f < 8; f++) {
#pragma unroll
            for (int off = 16; off >= 1; off >>= 1) {
                aq[t][f] += __shfl_xor_sync(0xffffffffu, aq[t][f], off);
                ak[t][f] += __shfl_xor_sync(0xffffffffu, ak[t][f], off);
            }
        }
        if (lane == 0) {
            float* qo = g_Q + (size_t)(tok0 + t) * 8;
            float* ko = g_K + (size_t)(tok0 + t) * 8;
            *(float4*)(qo)     = make_float4(aq[t][0], aq[t][1], aq[t][2], aq[t][3]);
            *(float4*)(qo + 4) = make_float4(aq[t][4], aq[t][5], aq[t][6], aq[t][7]);
            *(float4*)(ko)     = make_float4(ak[t][0], ak[t][1], ak[t][2], ak[t][3]);
            *(float4*)(ko + 4) = make_float4(ak[t][4], ak[t][5], ak[t][6], ak[t][7]);
        }
    }
}

// ---------------------------------------------------------------------------
// Kernel 2: V = X @ Wv.  Classic fp32 SGEMM (exact R1 version: known-good).
// BM=BN=128, BK=16, 256 threads, 8x8 register micro-tiles.
// ---------------------------------------------------------------------------
__global__ __launch_bounds__(256) void vproj_kernel(const float* __restrict__ A,
                                                    const float* __restrict__ Bw) {
    __shared__ float As[16][132];
    __shared__ float Bs[16][128];

    int t  = threadIdx.x;
    int bm = blockIdx.y;
    int bn = blockIdx.x;
    int tr = t >> 4;
    int tc = t & 15;

    const float* Ag = A + (size_t)bm * 128 * DIN;
    const float* Bg = Bw + (size_t)bn * 128;

    float acc[8][8];
#pragma unroll
    for (int i = 0; i < 8; i++)
#pragma unroll
        for (int j = 0; j < 8; j++) acc[i][j] = 0.f;

    for (int kt = 0; kt < DIN; kt += 16) {
#pragma unroll
        for (int e = t; e < 512; e += 256) {
            int row = e >> 2;
            int cg  = (e & 3) << 2;
            float4 v = *(const float4*)(Ag + (size_t)row * DIN + kt + cg);
            As[cg + 0][row] = v.x;
            As[cg + 1][row] = v.y;
            As[cg + 2][row] = v.z;
            As[cg + 3][row] = v.w;
        }
#pragma unroll
        for (int e = t; e < 512; e += 256) {
            int row = e >> 5;
            int cg  = (e & 31) << 2;
            *(float4*)(&Bs[row][cg]) =
                *(const float4*)(Bg + (size_t)(kt + row) * DOUT + cg);
        }
        __syncthreads();

#pragma unroll
        for (int k = 0; k < 16; k++) {
            float a0[8], b0[8];
            *(float4*)(a0)     = *(const float4*)(&As[k][tr * 4]);
            *(float4*)(a0 + 4) = *(const float4*)(&As[k][tr * 4 + 64]);
            *(float4*)(b0)     = *(const float4*)(&Bs[k][tc * 4]);
            *(float4*)(b0 + 4) = *(const float4*)(&Bs[k][tc * 4 + 64]);
#pragma unroll
            for (int i = 0; i < 8; i++)
#pragma unroll
                for (int j = 0; j < 8; j++)
                    acc[i][j] += a0[i] * b0[j];
        }
        __syncthreads();
    }

#pragma unroll
    for (int i = 0; i < 8; i++) {
        int rr = tr * 4 + ((i & 4) ? 64 : 0) + (i & 3);
        float* cp = g_V + (size_t)(bm * 128 + rr) * DOUT + bn * 128;
        *(float4*)(cp + tc * 4)      = make_float4(acc[i][0], acc[i][1], acc[i][2], acc[i][3]);
        *(float4*)(cp + tc * 4 + 64) = make_float4(acc[i][4], acc[i][5], acc[i][6], acc[i][7]);
    }
}

// ---------------------------------------------------------------------------
// Kernel 3: sparse-softmax attention, recompute variant (NO score storage).
// CTA stages its batch's K transposed ([8][2048]) in 64KB smem.
// Pass 1: recomputable 8-FMA dot per key -> row max m (registers: ~10).
// Pass 2: recompute dot, ballot d8 > m-23 (p > 1e-10), gather V rows +
// exp only for survivors. p is identical across lanes (shfl broadcast),
// so psum needs no reduction. Dropped tail mass <= 2048e-10 ~ 2e-7,
// identical in numerator and denominator.
// ---------------------------------------------------------------------------
__global__ __launch_bounds__(256) void attn_kernel(float* __restrict__ Out) {
    extern __shared__ float Kt[];   // [8][2048]
    int tid  = threadIdx.x;
    int warp = tid >> 5;
    int lane = tid & 31;
    int q0   = blockIdx.x * 32;
    int b    = q0 >> 11;
    const float* Kb = g_K + (size_t)b * T_ * DA;
    const float* Vb = g_V + (size_t)b * T_ * DOUT;

    // Stage K transposed: Kt[f][s], conflict-free scalar LDS later.
    for (int idx = tid; idx < 4096; idx += 256) {
        int row = idx >> 1;
        int h   = (idx & 1) * 4;
        float4 v = *(const float4*)(Kb + (size_t)row * 8 + h);
        Kt[(h + 0) * 2048 + row] = v.x;
        Kt[(h + 1) * 2048 + row] = v.y;
        Kt[(h + 2) * 2048 + row] = v.z;
        Kt[(h + 3) * 2048 + row] = v.w;
    }
    __syncthreads();

#pragma unroll 1
    for (int qi = 0; qi < 4; qi++) {
        int q = q0 + warp * 4 + qi;
        float qv[8];
#pragma unroll
        for (int f = 0; f < 8; f++) qv[f] = g_Q[(size_t)q * 8 + f];

        // ---- Pass 1: row max of d^8 ----
        float m = -INFINITY;
#pragma unroll 4
        for (int i = 0; i < 64; i++) {
            int s = i * 32 + lane;
            float d = qv[0] * Kt[s];
#pragma unroll
            for (int f = 1; f < 8; f++) d += qv[f] * Kt[f * 2048 + s];
            float d2 = d * d;
            float d4 = d2 * d2;
            float d8 = d4 * d4;
            m = fmaxf(m, d8);
        }
#pragma unroll
        for (int off = 16; off >= 1; off >>= 1)
            m = fmaxf(m, __shfl_xor_sync(0xffffffffu, m, off));

        float thr = m - 23.0f;   // exp(-23) ~ 1e-10
        float acc[16];
#pragma unroll
        for (int j = 0; j < 16; j++) acc[j] = 0.f;
        float psum = 0.f;

        // ---- Pass 2: recompute, gather survivors ----
#pragma unroll 2
        for (int i = 0; i < 64; i++) {
            int s = i * 32 + lane;
            float d = qv[0] * Kt[s];
#pragma unroll
            for (int f = 1; f < 8; f++) d += qv[f] * Kt[f * 2048 + s];
            float d2 = d * d;
            float d4 = d2 * d2;
            float d8 = d4 * d4;
            unsigned ball = __ballot_sync(0xffffffffu, d8 > thr);
            while (ball) {
                int src = __ffs(ball) - 1;
                ball &= ball - 1;
                float d8s = __shfl_sync(0xffffffffu, d8, src);
                float p = __expf(d8s - m);   // identical in all lanes
                psum += p;
                int sk = i * 32 + src;
                const float4* vp = (const float4*)(Vb + (size_t)sk * DOUT) + lane * 4;
                float4 v0 = vp[0];
                float4 v1 = vp[1];
                float4 v2 = vp[2];
                float4 v3 = vp[3];
                acc[0]  += p * v0.x; acc[1]  += p * v0.y; acc[2]  += p * v0.z; acc[3]  += p * v0.w;
                acc[4]  += p * v1.x; acc[5]  += p * v1.y; acc[6]  += p * v1.z; acc[7]  += p * v1.w;
                acc[8]  += p * v2.x; acc[9]  += p * v2.y; acc[10] += p * v2.z; acc[11] += p * v2.w;
                acc[12] += p * v3.x; acc[13] += p * v3.y; acc[14] += p * v3.z; acc[15] += p * v3.w;
            }
        }

        float inv = 1.f / psum;   // psum identical across lanes
        float4* op = (float4*)(Out + (size_t)q * DOUT) + lane * 4;
        op[0] = make_float4(acc[0]  * inv, acc[1]  * inv, acc[2]  * inv, acc[3]  * inv);
        op[1] = make_float4(acc[4]  * inv, acc[5]  * inv, acc[6]  * inv, acc[7]  * inv);
        op[2] = make_float4(acc[8]  * inv, acc[9]  * inv, acc[10] * inv, acc[11] * inv);
        op[3] = make_float4(acc[12] * inv, acc[13] * inv, acc[14] * inv, acc[15] * inv);
    }
}

// ---------------------------------------------------------------------------
extern "C" void kernel_launch(void* const* d_in, const int* in_sizes, int n_in,
                              void* d_out, int out_size) {
    (void)in_sizes; (void)n_in; (void)out_size;
    const float* X  = (const float*)d_in[0];
    const float* Wq = (const float*)d_in[1];
    const float* Wk = (const float*)d_in[2];
    const float* Wv = (const float*)d_in[3];
    float* Out = (float*)d_out;

    cudaFuncSetAttribute(attn_kernel,
                         cudaFuncAttributeMaxDynamicSharedMemorySize, 65536);

    qk_kernel<<<(B_ * T_) / 32, 256>>>(X, Wq, Wk);
    vproj_kernel<<<dim3(DOUT / 128, (B_ * T_) / 128), 256>>>(X, Wv);
    attn_kernel<<<(B_ * T_) / 32, 256, 65536>>>(Out);
}

// round 4
// speedup vs baseline: 2.2315x; 2.2315x over previous
#include <cuda_runtime.h>
#include <math.h>

#define B_    8
#define T_    2048
#define DIN   512
#define DA    8
#define DOUT  512

__device__ __align__(16) float g_Q[B_ * T_ * DA];
__device__ __align__(16) float g_K[B_ * T_ * DA];
__device__ __align__(16) float g_V[B_ * T_ * DOUT];

// ---------------------------------------------------------------------------
// Kernel 1: V = X @ Wv. Classic fp32 SGEMM, BM=BN=128, BK=16, 256 threads,
// 8x8 register micro-tiles. Launched FIRST so ncu's fixed launch slot
// profiles it. __launch_bounds__(256,2) forces >=2 CTAs/SM (<=128 regs).
// ---------------------------------------------------------------------------
__global__ __launch_bounds__(256, 2) void vproj_kernel(const float* __restrict__ A,
                                                       const float* __restrict__ Bw) {
    __shared__ float As[16][132];
    __shared__ float Bs[16][128];

    int t  = threadIdx.x;
    int bm = blockIdx.y;
    int bn = blockIdx.x;
    int tr = t >> 4;
    int tc = t & 15;

    const float* Ag = A + (size_t)bm * 128 * DIN;
    const float* Bg = Bw + (size_t)bn * 128;

    float acc[8][8];
#pragma unroll
    for (int i = 0; i < 8; i++)
#pragma unroll
        for (int j = 0; j < 8; j++) acc[i][j] = 0.f;

    for (int kt = 0; kt < DIN; kt += 16) {
#pragma unroll
        for (int e = t; e < 512; e += 256) {
            int row = e >> 2;
            int cg  = (e & 3) << 2;
            float4 v = *(const float4*)(Ag + (size_t)row * DIN + kt + cg);
            As[cg + 0][row] = v.x;
            As[cg + 1][row] = v.y;
            As[cg + 2][row] = v.z;
            As[cg + 3][row] = v.w;
        }
#pragma unroll
        for (int e = t; e < 512; e += 256) {
            int row = e >> 5;
            int cg  = (e & 31) << 2;
            *(float4*)(&Bs[row][cg]) =
                *(const float4*)(Bg + (size_t)(kt + row) * DOUT + cg);
        }
        __syncthreads();

#pragma unroll
        for (int k = 0; k < 16; k++) {
            float a0[8], b0[8];
            *(float4*)(a0)     = *(const float4*)(&As[k][tr * 4]);
            *(float4*)(a0 + 4) = *(const float4*)(&As[k][tr * 4 + 64]);
            *(float4*)(b0)     = *(const float4*)(&Bs[k][tc * 4]);
            *(float4*)(b0 + 4) = *(const float4*)(&Bs[k][tc * 4 + 64]);
#pragma unroll
            for (int i = 0; i < 8; i++)
#pragma unroll
                for (int j = 0; j < 8; j++)
                    acc[i][j] += a0[i] * b0[j];
        }
        __syncthreads();
    }

#pragma unroll
    for (int i = 0; i < 8; i++) {
        int rr = tr * 4 + ((i & 4) ? 64 : 0) + (i & 3);
        float* cp = g_V + (size_t)(bm * 128 + rr) * DOUT + bn * 128;
        *(float4*)(cp + tc * 4)      = make_float4(acc[i][0], acc[i][1], acc[i][2], acc[i][3]);
        *(float4*)(cp + tc * 4 + 64) = make_float4(acc[i][4], acc[i][5], acc[i][6], acc[i][7]);
    }
}

// ---------------------------------------------------------------------------
// Kernel 2: Q,K projections. One warp per 4 tokens (measured: ~35us).
// ---------------------------------------------------------------------------
__global__ __launch_bounds__(256) void qk_kernel(const float* __restrict__ X,
                                                 const float* __restrict__ Wq,
                                                 const float* __restrict__ Wk) {
    int warp = threadIdx.x >> 5;
    int lane = threadIdx.x & 31;
    int tok0 = blockIdx.x * 32 + warp * 4;

    float aq[4][8], ak[4][8];
#pragma unroll
    for (int t = 0; t < 4; t++)
#pragma unroll
        for (int f = 0; f < 8; f++) { aq[t][f] = 0.f; ak[t][f] = 0.f; }

#pragma unroll 4
    for (int d = lane; d < DIN; d += 32) {
        float xv[4];
#pragma unroll
        for (int t = 0; t < 4; t++) xv[t] = X[(size_t)(tok0 + t) * DIN + d];
        float4 q0 = *(const float4*)(Wq + (size_t)d * 8);
        float4 q1 = *(const float4*)(Wq + (size_t)d * 8 + 4);
        float4 k0 = *(const float4*)(Wk + (size_t)d * 8);
        float4 k1 = *(const float4*)(Wk + (size_t)d * 8 + 4);
#pragma unroll
        for (int t = 0; t < 4; t++) {
            aq[t][0] += xv[t] * q0.x; aq[t][1] += xv[t] * q0.y;
            aq[t][2] += xv[t] * q0.z; aq[t][3] += xv[t] * q0.w;
            aq[t][4] += xv[t] * q1.x; aq[t][5] += xv[t] * q1.y;
            aq[t][6] += xv[t] * q1.z; aq[t][7] += xv[t] * q1.w;
            ak[t][0] += xv[t] * k0.x; ak[t][1] += xv[t] * k0.y;
            ak[t][2] += xv[t] * k0.z; ak[t][3] += xv[t] * k0.w;
            ak[t][4] += xv[t] * k1.x; ak[t][5] += xv[t] * k1.y;
            ak[t][6] += xv[t] * k1.z; ak[t][7] += xv[t] * k1.w;
        }
    }

#pragma unroll
    for (int t = 0; t < 4; t++) {
#pragma unroll
        for (int f = 0; f < 8; f++) {
#pragma unroll
            for (int off = 16; off >= 1; off >>= 1) {
                aq[t][f] += __shfl_xor_sync(0xffffffffu, aq[t][f], off);
                ak[t][f] += __shfl_xor_sync(0xffffffffu, ak[t][f], off);
            }
        }
        if (lane == 0) {
            float* qo = g_Q + (size_t)(tok0 + t) * 8;
            float* ko = g_K + (size_t)(tok0 + t) * 8;
            *(float4*)(qo)     = make_float4(aq[t][0], aq[t][1], aq[t][2], aq[t][3]);
            *(float4*)(qo + 4) = make_float4(aq[t][4], aq[t][5], aq[t][6], aq[t][7]);
            *(float4*)(ko)     = make_float4(ak[t][0], ak[t][1], ak[t][2], ak[t][3]);
            *(float4*)(ko + 4) = make_float4(ak[t][4], ak[t][5], ak[t][6], ak[t][7]);
        }
    }
}

// ---------------------------------------------------------------------------
// Kernel 3: attention — EXACT R1 structure (grid 2048, one query per warp,
// K coalesced from L2, s8v[64] in local, same pragmas), with ONE change:
// pass 2 ballots on s8v[i] > m-23 FIRST and computes exp only for the ~2
// surviving keys (p identical across lanes via shfl, so psum needs no
// reduction). Sub-threshold terms (p < 1e-10) are dropped from both the
// numerator and denominator: relative perturbation <= 2048e-10 ~ 2e-7.
// ---------------------------------------------------------------------------
__global__ __launch_bounds__(256) void attn_kernel(float* __restrict__ Out) {
    int warp = threadIdx.x >> 5;
    int lane = threadIdx.x & 31;
    int q    = blockIdx.x * 8 + warp;          // 0..16383
    int b    = q >> 11;
    const float* Kb = g_K + (size_t)b * T_ * DA;
    const float* Vb = g_V + (size_t)b * T_ * DOUT;

    float4 qa = *(const float4*)(g_Q + (size_t)q * DA);
    float4 qb = *(const float4*)(g_Q + (size_t)q * DA + 4);

    float s8v[64];
    float m = -INFINITY;

#pragma unroll 1
    for (int i = 0; i < 64; i++) {
        int s = i * 32 + lane;                 // coalesced K rows
        const float4* kp = (const float4*)(Kb + (size_t)s * DA);
        float4 k0 = kp[0];
        float4 k1 = kp[1];
        float d = qa.x * k0.x + qa.y * k0.y + qa.z * k0.z + qa.w * k0.w
                + qb.x * k1.x + qb.y * k1.y + qb.z * k1.z + qb.w * k1.w;
        float d2 = d * d;
        float d4 = d2 * d2;
        float d8 = d4 * d4;
        s8v[i] = d8;
        m = fmaxf(m, d8);
    }
    m = fmaxf(m, __shfl_xor_sync(0xffffffffu, m, 16));
    m = fmaxf(m, __shfl_xor_sync(0xffffffffu, m, 8));
    m = fmaxf(m, __shfl_xor_sync(0xffffffffu, m, 4));
    m = fmaxf(m, __shfl_xor_sync(0xffffffffu, m, 2));
    m = fmaxf(m, __shfl_xor_sync(0xffffffffu, m, 1));

    float thr = m - 23.0f;                     // exp(-23) ~ 1e-10

    float acc0 = 0.f, acc1 = 0.f, acc2 = 0.f, acc3 = 0.f;
    float acc4 = 0.f, acc5 = 0.f, acc6 = 0.f, acc7 = 0.f;
    float acc8 = 0.f, acc9 = 0.f, accA = 0.f, accB = 0.f;
    float accC = 0.f, accD = 0.f, accE = 0.f, accF = 0.f;
    float psum = 0.f;

#pragma unroll 1
    for (int i = 0; i < 64; i++) {
        float d8 = s8v[i];
        unsigned ball = __ballot_sync(0xffffffffu, d8 > thr);
        while (ball) {
            int src = __ffs(ball) - 1;
            ball &= ball - 1;
            float d8s = __shfl_sync(0xffffffffu, d8, src);
            float p = __expf(d8s - m);         // identical in all lanes
            psum += p;
            int s = i * 32 + src;
            const float4* vp = (const float4*)(Vb + (size_t)s * DOUT) + lane * 4;
            float4 v0 = vp[0];
            float4 v1 = vp[1];
            float4 v2 = vp[2];
            float4 v3 = vp[3];
            acc0 += p * v0.x; acc1 += p * v0.y; acc2 += p * v0.z; acc3 += p * v0.w;
            acc4 += p * v1.x; acc5 += p * v1.y; acc6 += p * v1.z; acc7 += p * v1.w;
            acc8 += p * v2.x; acc9 += p * v2.y; accA += p * v2.z; accB += p * v2.w;
            accC += p * v3.x; accD += p * v3.y; accE += p * v3.z; accF += p * v3.w;
        }
    }

    float inv = 1.f / psum;                    // psum identical across lanes

    float4* op = (float4*)(Out + (size_t)q * DOUT) + lane * 4;
    op[0] = make_float4(acc0 * inv, acc1 * inv, acc2 * inv, acc3 * inv);
    op[1] = make_float4(acc4 * inv, acc5 * inv, acc6 * inv, acc7 * inv);
    op[2] = make_float4(acc8 * inv, acc9 * inv, accA * inv, accB * inv);
    op[3] = make_float4(accC * inv, accD * inv, accE * inv, accF * inv);
}

// ---------------------------------------------------------------------------
extern "C" void kernel_launch(void* const* d_in, const int* in_sizes, int n_in,
                              void* d_out, int out_size) {
    (void)in_sizes; (void)n_in; (void)out_size;
    const float* X  = (const float*)d_in[0];
    const float* Wq = (const float*)d_in[1];
    const float* Wk = (const float*)d_in[2];
    const float* Wv = (const float*)d_in[3];
    float* Out = (float*)d_out;

    // vproj first so the profiler's fixed launch slot captures it
    vproj_kernel<<<dim3(DOUT / 128, (B_ * T_) / 128), 256>>>(X, Wv);
    qk_kernel<<<(B_ * T_) / 32, 256>>>(X, Wq, Wk);
    attn_kernel<<<(B_ * T_) / 8, 256>>>(Out);
}

// round 5
// speedup vs baseline: 2.7719x; 1.2421x over previous
#include <cuda_runtime.h>
#include <math.h>

#define B_    8
#define T_    2048
#define DIN   512
#define DA    8
#define DOUT  512
#define NCAP  64          // survivor cap for the sparse gather path
#define DGRP  16          // dense queries per CTA group
#define DSLOT 16          // dense CTAs per batch

__device__ __align__(16) float g_Q[B_ * T_ * DA];
__device__ __align__(16) float g_K[B_ * T_ * DA];
__device__ __align__(16) float g_V[B_ * T_ * DOUT];
__device__ float g_m[B_ * T_];          // per-query max of d^8
__device__ int   g_dcount[B_];          // dense-queue counts
__device__ int   g_dq[B_ * T_];         // dense-queue (local q indices per batch)

// ---------------------------------------------------------------------------
__global__ void zero_kernel() {
    if (threadIdx.x < B_) g_dcount[threadIdx.x] = 0;
}

// ---------------------------------------------------------------------------
// V = X @ Wv. fp32 SGEMM, measured 215us (fma 56%, issue 71%). Unchanged.
// ---------------------------------------------------------------------------
__global__ __launch_bounds__(256, 2) void vproj_kernel(const float* __restrict__ A,
                                                       const float* __restrict__ Bw) {
    __shared__ float As[16][132];
    __shared__ float Bs[16][128];

    int t  = threadIdx.x;
    int bm = blockIdx.y;
    int bn = blockIdx.x;
    int tr = t >> 4;
    int tc = t & 15;

    const float* Ag = A + (size_t)bm * 128 * DIN;
    const float* Bg = Bw + (size_t)bn * 128;

    float acc[8][8];
#pragma unroll
    for (int i = 0; i < 8; i++)
#pragma unroll
        for (int j = 0; j < 8; j++) acc[i][j] = 0.f;

    for (int kt = 0; kt < DIN; kt += 16) {
#pragma unroll
        for (int e = t; e < 512; e += 256) {
            int row = e >> 2;
            int cg  = (e & 3) << 2;
            float4 v = *(const float4*)(Ag + (size_t)row * DIN + kt + cg);
            As[cg + 0][row] = v.x;
            As[cg + 1][row] = v.y;
            As[cg + 2][row] = v.z;
            As[cg + 3][row] = v.w;
        }
#pragma unroll
        for (int e = t; e < 512; e += 256) {
            int row = e >> 5;
            int cg  = (e & 31) << 2;
            *(float4*)(&Bs[row][cg]) =
                *(const float4*)(Bg + (size_t)(kt + row) * DOUT + cg);
        }
        __syncthreads();

#pragma unroll
        for (int k = 0; k < 16; k++) {
            float a0[8], b0[8];
            *(float4*)(a0)     = *(const float4*)(&As[k][tr * 4]);
            *(float4*)(a0 + 4) = *(const float4*)(&As[k][tr * 4 + 64]);
            *(float4*)(b0)     = *(const float4*)(&Bs[k][tc * 4]);
            *(float4*)(b0 + 4) = *(const float4*)(&Bs[k][tc * 4 + 64]);
#pragma unroll
            for (int i = 0; i < 8; i++)
#pragma unroll
                for (int j = 0; j < 8; j++)
                    acc[i][j] += a0[i] * b0[j];
        }
        __syncthreads();
    }

#pragma unroll
    for (int i = 0; i < 8; i++) {
        int rr = tr * 4 + ((i & 4) ? 64 : 0) + (i & 3);
        float* cp = g_V + (size_t)(bm * 128 + rr) * DOUT + bn * 128;
        *(float4*)(cp + tc * 4)      = make_float4(acc[i][0], acc[i][1], acc[i][2], acc[i][3]);
        *(float4*)(cp + tc * 4 + 64) = make_float4(acc[i][4], acc[i][5], acc[i][6], acc[i][7]);
    }
}

// ---------------------------------------------------------------------------
// Q,K projections (measured ~35us). Unchanged.
// ---------------------------------------------------------------------------
__global__ __launch_bounds__(256) void qk_kernel(const float* __restrict__ X,
                                                 const float* __restrict__ Wq,
                                                 const float* __restrict__ Wk) {
    int warp = threadIdx.x >> 5;
    int lane = threadIdx.x & 31;
    int tok0 = blockIdx.x * 32 + warp * 4;

    float aq[4][8], ak[4][8];
#pragma unroll
    for (int t = 0; t < 4; t++)
#pragma unroll
        for (int f = 0; f < 8; f++) { aq[t][f] = 0.f; ak[t][f] = 0.f; }

#pragma unroll 4
    for (int d = lane; d < DIN; d += 32) {
        float xv[4];
#pragma unroll
        for (int t = 0; t < 4; t++) xv[t] = X[(size_t)(tok0 + t) * DIN + d];
        float4 q0 = *(const float4*)(Wq + (size_t)d * 8);
        float4 q1 = *(const float4*)(Wq + (size_t)d * 8 + 4);
        float4 k0 = *(const float4*)(Wk + (size_t)d * 8);
        float4 k1 = *(const float4*)(Wk + (size_t)d * 8 + 4);
#pragma unroll
        for (int t = 0; t < 4; t++) {
            aq[t][0] += xv[t] * q0.x; aq[t][1] += xv[t] * q0.y;
            aq[t][2] += xv[t] * q0.z; aq[t][3] += xv[t] * q0.w;
            aq[t][4] += xv[t] * q1.x; aq[t][5] += xv[t] * q1.y;
            aq[t][6] += xv[t] * q1.z; aq[t][7] += xv[t] * q1.w;
            ak[t][0] += xv[t] * k0.x; ak[t][1] += xv[t] * k0.y;
            ak[t][2] += xv[t] * k0.z; ak[t][3] += xv[t] * k0.w;
            ak[t][4] += xv[t] * k1.x; ak[t][5] += xv[t] * k1.y;
            ak[t][6] += xv[t] * k1.z; ak[t][7] += xv[t] * k1.w;
        }
    }

#pragma unroll
    for (int t = 0; t < 4; t++) {
#pragma unroll
        for (int f = 0; f < 8; f++) {
#pragma unroll
            for (int off = 16; off >= 1; off >>= 1) {
                aq[t][f] += __shfl_xor_sync(0xffffffffu, aq[t][f], off);
                ak[t][f] += __shfl_xor_sync(0xffffffffu, ak[t][f], off);
            }
        }
        if (lane == 0) {
            float* qo = g_Q + (size_t)(tok0 + t) * 8;
            float* ko = g_K + (size_t)(tok0 + t) * 8;
            *(float4*)(qo)     = make_float4(aq[t][0], aq[t][1], aq[t][2], aq[t][3]);
            *(float4*)(qo + 4) = make_float4(aq[t][4], aq[t][5], aq[t][6], aq[t][7]);
            *(float4*)(ko)     = make_float4(ak[t][0], ak[t][1], ak[t][2], ak[t][3]);
            *(float4*)(ko + 4) = make_float4(ak[t][4], ak[t][5], ak[t][6], ak[t][7]);
        }
    }
}

// ---------------------------------------------------------------------------
// Sparse attention (one query per warp). Pass 1: scan, m. Pass 2a: count
// survivors n. If n <= NCAP: gather (dropped mass <= 2048e-10 ~ 2e-7,
// consistent in numerator and denominator). Else enqueue for dense kernel.
// ---------------------------------------------------------------------------
__global__ __launch_bounds__(256) void attn_sparse_kernel(float* __restrict__ Out) {
    int warp = threadIdx.x >> 5;
    int lane = threadIdx.x & 31;
    int q    = blockIdx.x * 8 + warp;
    int b    = q >> 11;
    const float* Kb = g_K + (size_t)b * T_ * DA;
    const float* Vb = g_V + (size_t)b * T_ * DOUT;

    float4 qa = *(const float4*)(g_Q + (size_t)q * DA);
    float4 qb = *(const float4*)(g_Q + (size_t)q * DA + 4);

    float s8v[64];
    float m = -INFINITY;

#pragma unroll 1
    for (int i = 0; i < 64; i++) {
        int s = i * 32 + lane;
        const float4* kp = (const float4*)(Kb + (size_t)s * DA);
        float4 k0 = kp[0];
        float4 k1 = kp[1];
        float d = qa.x * k0.x + qa.y * k0.y + qa.z * k0.z + qa.w * k0.w
                + qb.x * k1.x + qb.y * k1.y + qb.z * k1.z + qb.w * k1.w;
        float d2 = d * d;
        float d4 = d2 * d2;
        float d8 = d4 * d4;
        s8v[i] = d8;
        m = fmaxf(m, d8);
    }
#pragma unroll
    for (int off = 16; off >= 1; off >>= 1)
        m = fmaxf(m, __shfl_xor_sync(0xffffffffu, m, off));

    if (lane == 0) g_m[q] = m;

    float thr = m - 23.0f;

    // Pass 2a: survivor count
    int n = 0;
#pragma unroll 1
    for (int i = 0; i < 64; i++)
        n += __popc(__ballot_sync(0xffffffffu, s8v[i] > thr));

    if (n > NCAP) {
        if (lane == 0) {
            int idx = atomicAdd(&g_dcount[b], 1);
            g_dq[b * T_ + idx] = q & (T_ - 1);
        }
        return;
    }

    // Pass 2b: sparse gather
    float acc0 = 0.f, acc1 = 0.f, acc2 = 0.f, acc3 = 0.f;
    float acc4 = 0.f, acc5 = 0.f, acc6 = 0.f, acc7 = 0.f;
    float acc8 = 0.f, acc9 = 0.f, accA = 0.f, accB = 0.f;
    float accC = 0.f, accD = 0.f, accE = 0.f, accF = 0.f;
    float psum = 0.f;

#pragma unroll 1
    for (int i = 0; i < 64; i++) {
        float d8 = s8v[i];
        unsigned ball = __ballot_sync(0xffffffffu, d8 > thr);
        while (ball) {
            int src = __ffs(ball) - 1;
            ball &= ball - 1;
            float d8s = __shfl_sync(0xffffffffu, d8, src);
            float p = __expf(d8s - m);     // identical in all lanes
            psum += p;
            int s = i * 32 + src;
            const float4* vp = (const float4*)(Vb + (size_t)s * DOUT) + lane * 4;
            float4 v0 = vp[0];
            float4 v1 = vp[1];
            float4 v2 = vp[2];
            float4 v3 = vp[3];
            acc0 += p * v0.x; acc1 += p * v0.y; acc2 += p * v0.z; acc3 += p * v0.w;
            acc4 += p * v1.x; acc5 += p * v1.y; acc6 += p * v1.z; acc7 += p * v1.w;
            acc8 += p * v2.x; acc9 += p * v2.y; accA += p * v2.z; accB += p * v2.w;
            accC += p * v3.x; accD += p * v3.y; accE += p * v3.z; accF += p * v3.w;
        }
    }

    float inv = 1.f / psum;
    float4* op = (float4*)(Out + (size_t)q * DOUT) + lane * 4;
    op[0] = make_float4(acc0 * inv, acc1 * inv, acc2 * inv, acc3 * inv);
    op[1] = make_float4(acc4 * inv, acc5 * inv, acc6 * inv, acc7 * inv);
    op[2] = make_float4(acc8 * inv, acc9 * inv, accA * inv, accB * inv);
    op[3] = make_float4(accC * inv, accD * inv, accE * inv, accF * inv);
}

// ---------------------------------------------------------------------------
// Dense attention for queued queries: exact softmax over all 2048 keys.
// Grid = B_ * DSLOT CTAs of 256 threads. Each CTA processes groups of
// DGRP=16 queries (same batch) so every V row read is shared by 16 queries.
// Per 32-key chunk: warp w computes p for queries 2w,2w+1 (lane = key) into
// smem; then all 8 warps stream the 32 V rows, warp w owning output columns
// [64w, 64w+64), each lane a float2.
// ---------------------------------------------------------------------------
__global__ __launch_bounds__(256) void attn_dense_kernel(float* __restrict__ Out) {
    __shared__ float p_s[DGRP][33];
    __shared__ float psum_s[DGRP];
    __shared__ int   qq_s[DGRP];

    int b    = blockIdx.x >> 4;        // DSLOT = 16
    int slot = blockIdx.x & 15;
    int tid  = threadIdx.x;
    int warp = tid >> 5;
    int lane = tid & 31;

    int count = g_dcount[b];
    const float*  Kb  = g_K + (size_t)b * T_ * DA;
    const float2* Vb2 = (const float2*)(g_V + (size_t)b * T_ * DOUT);

    for (int g = slot; g * DGRP < count; g += DSLOT) {
        int ng = count - g * DGRP;
        if (ng > DGRP) ng = DGRP;

        if (tid < DGRP)
            qq_s[tid] = (tid < ng) ? g_dq[b * T_ + g * DGRP + tid] : 0;
        __syncthreads();

        // P-warp state: queries 2w, 2w+1
        int q0i = 2 * warp;
        int q1i = 2 * warp + 1;
        bool v0 = q0i < ng;
        bool v1 = q1i < ng;
        int gq0 = b * T_ + qq_s[v0 ? q0i : 0];
        int gq1 = b * T_ + qq_s[v1 ? q1i : 0];
        float qv0[8], qv1[8], m0, m1;
#pragma unroll
        for (int f = 0; f < 8; f++) {
            qv0[f] = g_Q[(size_t)gq0 * DA + f];
            qv1[f] = g_Q[(size_t)gq1 * DA + f];
        }
        m0 = g_m[gq0];
        m1 = g_m[gq1];
        float ps0 = 0.f, ps1 = 0.f;

        float2 acc[DGRP];
#pragma unroll
        for (int j = 0; j < DGRP; j++) acc[j] = make_float2(0.f, 0.f);

        for (int c = 0; c < T_ / 32; c++) {
            int k = c * 32 + lane;
            const float4* kp = (const float4*)(Kb + (size_t)k * DA);
            float4 k0 = kp[0];
            float4 k1 = kp[1];
            float d0 = qv0[0]*k0.x + qv0[1]*k0.y + qv0[2]*k0.z + qv0[3]*k0.w
                     + qv0[4]*k1.x + qv0[5]*k1.y + qv0[6]*k1.z + qv0[7]*k1.w;
            float d1 = qv1[0]*k0.x + qv1[1]*k0.y + qv1[2]*k0.z + qv1[3]*k0.w
                     + qv1[4]*k1.x + qv1[5]*k1.y + qv1[6]*k1.z + qv1[7]*k1.w;
            float e0 = d0 * d0; e0 = e0 * e0; e0 = e0 * e0;
            float e1 = d1 * d1; e1 = e1 * e1; e1 = e1 * e1;
            float p0 = v0 ? __expf(e0 - m0) : 0.f;
            float p1 = v1 ? __expf(e1 - m1) : 0.f;
            ps0 += p0;
            ps1 += p1;
            p_s[q0i][lane] = p0;
            p_s[q1i][lane] = p1;
            __syncthreads();

            // V phase: warp w owns columns [64w, 64w+64); lane -> 2 cols
            const float2* vcol = Vb2 + (size_t)(c * 32) * 256 + warp * 32 + lane;
#pragma unroll 4
            for (int kk = 0; kk < 32; kk++) {
                float2 v = vcol[(size_t)kk * 256];
#pragma unroll
                for (int j = 0; j < DGRP; j++) {
                    float p = p_s[j][kk];
                    acc[j].x += p * v.x;
                    acc[j].y += p * v.y;
                }
            }
            __syncthreads();
        }

        // psum reduce and publish
#pragma unroll
        for (int off = 16; off >= 1; off >>= 1) {
            ps0 += __shfl_xor_sync(0xffffffffu, ps0, off);
            ps1 += __shfl_xor_sync(0xffffffffu, ps1, off);
        }
        if (lane == 0) {
            if (v0) psum_s[q0i] = ps0;
            if (v1) psum_s[q1i] = ps1;
        }
        __syncthreads();

        for (int j = 0; j < ng; j++) {
            float inv = 1.f / psum_s[j];
            int gq = b * T_ + qq_s[j];
            float2* op = (float2*)(Out + (size_t)gq * DOUT) + warp * 32 + lane;
            *op = make_float2(acc[j].x * inv, acc[j].y * inv);
        }
        __syncthreads();
    }
}

// ---------------------------------------------------------------------------
extern "C" void kernel_launch(void* const* d_in, const int* in_sizes, int n_in,
                              void* d_out, int out_size) {
    (void)in_sizes; (void)n_in; (void)out_size;
    const float* X  = (const float*)d_in[0];
    const float* Wq = (const float*)d_in[1];
    const float* Wk = (const float*)d_in[2];
    const float* Wv = (const float*)d_in[3];
    float* Out = (float*)d_out;

    vproj_kernel<<<dim3(DOUT / 128, (B_ * T_) / 128), 256>>>(X, Wv);
    zero_kernel<<<1, 32>>>();
    qk_kernel<<<(B_ * T_) / 32, 256>>>(X, Wq, Wk);
    attn_sparse_kernel<<<(B_ * T_) / 8, 256>>>(Out);
    attn_dense_kernel<<<B_ * DSLOT, 256>>>(Out);
}

// round 6
// speedup vs baseline: 3.2372x; 1.1679x over previous
#include <cuda_runtime.h>
#include <math.h>

#define B_    8
#define T_    2048
#define DIN   512
#define DA    8
#define DOUT  512
#define NCAP  384         // survivor cap for the sparse gather path
#define DGRP  16          // dense queries per CTA group
#define DSLOT 32          // dense CTAs per batch

__device__ __align__(16) float g_Q[B_ * T_ * DA];
__device__ __align__(16) float g_K[B_ * T_ * DA];
__device__ __align__(16) float g_V[B_ * T_ * DOUT];
__device__ float g_m[B_ * T_];          // per-query max of d^8
__device__ int   g_dcount[B_];          // dense-queue counts
__device__ int   g_dq[B_ * T_];         // dense-queue (local q indices per batch)

// ---------------------------------------------------------------------------
__global__ void zero_kernel() {
    if (threadIdx.x < B_) g_dcount[threadIdx.x] = 0;
}

// ---------------------------------------------------------------------------
// V = X @ Wv. fp32 SGEMM, measured 215us (fma 56%, issue 71%). Unchanged.
// ---------------------------------------------------------------------------
__global__ __launch_bounds__(256, 2) void vproj_kernel(const float* __restrict__ A,
                                                       const float* __restrict__ Bw) {
    __shared__ float As[16][132];
    __shared__ float Bs[16][128];

    int t  = threadIdx.x;
    int bm = blockIdx.y;
    int bn = blockIdx.x;
    int tr = t >> 4;
    int tc = t & 15;

    const float* Ag = A + (size_t)bm * 128 * DIN;
    const float* Bg = Bw + (size_t)bn * 128;

    float acc[8][8];
#pragma unroll
    for (int i = 0; i < 8; i++)
#pragma unroll
        for (int j = 0; j < 8; j++) acc[i][j] = 0.f;

    for (int kt = 0; kt < DIN; kt += 16) {
#pragma unroll
        for (int e = t; e < 512; e += 256) {
            int row = e >> 2;
            int cg  = (e & 3) << 2;
            float4 v = *(const float4*)(Ag + (size_t)row * DIN + kt + cg);
            As[cg + 0][row] = v.x;
            As[cg + 1][row] = v.y;
            As[cg + 2][row] = v.z;
            As[cg + 3][row] = v.w;
        }
#pragma unroll
        for (int e = t; e < 512; e += 256) {
            int row = e >> 5;
            int cg  = (e & 31) << 2;
            *(float4*)(&Bs[row][cg]) =
                *(const float4*)(Bg + (size_t)(kt + row) * DOUT + cg);
        }
        __syncthreads();

#pragma unroll
        for (int k = 0; k < 16; k++) {
            float a0[8], b0[8];
            *(float4*)(a0)     = *(const float4*)(&As[k][tr * 4]);
            *(float4*)(a0 + 4) = *(const float4*)(&As[k][tr * 4 + 64]);
            *(float4*)(b0)     = *(const float4*)(&Bs[k][tc * 4]);
            *(float4*)(b0 + 4) = *(const float4*)(&Bs[k][tc * 4 + 64]);
#pragma unroll
            for (int i = 0; i < 8; i++)
#pragma unroll
                for (int j = 0; j < 8; j++)
                    acc[i][j] += a0[i] * b0[j];
        }
        __syncthreads();
    }

#pragma unroll
    for (int i = 0; i < 8; i++) {
        int rr = tr * 4 + ((i & 4) ? 64 : 0) + (i & 3);
        float* cp = g_V + (size_t)(bm * 128 + rr) * DOUT + bn * 128;
        *(float4*)(cp + tc * 4)      = make_float4(acc[i][0], acc[i][1], acc[i][2], acc[i][3]);
        *(float4*)(cp + tc * 4 + 64) = make_float4(acc[i][4], acc[i][5], acc[i][6], acc[i][7]);
    }
}

// ---------------------------------------------------------------------------
// Q,K projections (measured ~35us). Unchanged.
// ---------------------------------------------------------------------------
__global__ __launch_bounds__(256) void qk_kernel(const float* __restrict__ X,
                                                 const float* __restrict__ Wq,
                                                 const float* __restrict__ Wk) {
    int warp = threadIdx.x >> 5;
    int lane = threadIdx.x & 31;
    int tok0 = blockIdx.x * 32 + warp * 4;

    float aq[4][8], ak[4][8];
#pragma unroll
    for (int t = 0; t < 4; t++)
#pragma unroll
        for (int f = 0; f < 8; f++) { aq[t][f] = 0.f; ak[t][f] = 0.f; }

#pragma unroll 4
    for (int d = lane; d < DIN; d += 32) {
        float xv[4];
#pragma unroll
        for (int t = 0; t < 4; t++) xv[t] = X[(size_t)(tok0 + t) * DIN + d];
        float4 q0 = *(const float4*)(Wq + (size_t)d * 8);
        float4 q1 = *(const float4*)(Wq + (size_t)d * 8 + 4);
        float4 k0 = *(const float4*)(Wk + (size_t)d * 8);
        float4 k1 = *(const float4*)(Wk + (size_t)d * 8 + 4);
#pragma unroll
        for (int t = 0; t < 4; t++) {
            aq[t][0] += xv[t] * q0.x; aq[t][1] += xv[t] * q0.y;
            aq[t][2] += xv[t] * q0.z; aq[t][3] += xv[t] * q0.w;
            aq[t][4] += xv[t] * q1.x; aq[t][5] += xv[t] * q1.y;
            aq[t][6] += xv[t] * q1.z; aq[t][7] += xv[t] * q1.w;
            ak[t][0] += xv[t] * k0.x; ak[t][1] += xv[t] * k0.y;
            ak[t][2] += xv[t] * k0.z; ak[t][3] += xv[t] * k0.w;
            ak[t][4] += xv[t] * k1.x; ak[t][5] += xv[t] * k1.y;
            ak[t][6] += xv[t] * k1.z; ak[t][7] += xv[t] * k1.w;
        }
    }

#pragma unroll
    for (int t = 0; t < 4; t++) {
#pragma unroll
        for (int f = 0; f < 8; f++) {
#pragma unroll
            for (int off = 16; off >= 1; off >>= 1) {
                aq[t][f] += __shfl_xor_sync(0xffffffffu, aq[t][f], off);
                ak[t][f] += __shfl_xor_sync(0xffffffffu, ak[t][f], off);
            }
        }
        if (lane == 0) {
            float* qo = g_Q + (size_t)(tok0 + t) * 8;
            float* ko = g_K + (size_t)(tok0 + t) * 8;
            *(float4*)(qo)     = make_float4(aq[t][0], aq[t][1], aq[t][2], aq[t][3]);
            *(float4*)(qo + 4) = make_float4(aq[t][4], aq[t][5], aq[t][6], aq[t][7]);
            *(float4*)(ko)     = make_float4(ak[t][0], ak[t][1], ak[t][2], ak[t][3]);
            *(float4*)(ko + 4) = make_float4(ak[t][4], ak[t][5], ak[t][6], ak[t][7]);
        }
    }
}

// ---------------------------------------------------------------------------
// Sparse attention (one query per warp). Pass 1: scan, m. Pass 2a: count
// survivors n (keys with p > 1e-10). If n <= NCAP: ballot-walk gather.
// Else enqueue for dense kernel. Dropped mass <= 2048e-10 ~ 2e-7,
// removed consistently from numerator and denominator.
// ---------------------------------------------------------------------------
__global__ __launch_bounds__(256) void attn_sparse_kernel(float* __restrict__ Out) {
    int warp = threadIdx.x >> 5;
    int lane = threadIdx.x & 31;
    int q    = blockIdx.x * 8 + warp;
    int b    = q >> 11;
    const float* Kb = g_K + (size_t)b * T_ * DA;
    const float* Vb = g_V + (size_t)b * T_ * DOUT;

    float4 qa = *(const float4*)(g_Q + (size_t)q * DA);
    float4 qb = *(const float4*)(g_Q + (size_t)q * DA + 4);

    float s8v[64];
    float m = -INFINITY;

#pragma unroll 1
    for (int i = 0; i < 64; i++) {
        int s = i * 32 + lane;
        const float4* kp = (const float4*)(Kb + (size_t)s * DA);
        float4 k0 = kp[0];
        float4 k1 = kp[1];
        float d = qa.x * k0.x + qa.y * k0.y + qa.z * k0.z + qa.w * k0.w
                + qb.x * k1.x + qb.y * k1.y + qb.z * k1.z + qb.w * k1.w;
        float d2 = d * d;
        float d4 = d2 * d2;
        float d8 = d4 * d4;
        s8v[i] = d8;
        m = fmaxf(m, d8);
    }
#pragma unroll
    for (int off = 16; off >= 1; off >>= 1)
        m = fmaxf(m, __shfl_xor_sync(0xffffffffu, m, off));

    if (lane == 0) g_m[q] = m;

    float thr = m - 23.0f;

    // Pass 2a: survivor count
    int n = 0;
#pragma unroll 1
    for (int i = 0; i < 64; i++)
        n += __popc(__ballot_sync(0xffffffffu, s8v[i] > thr));

    if (n > NCAP) {
        if (lane == 0) {
            int idx = atomicAdd(&g_dcount[b], 1);
            g_dq[b * T_ + idx] = q & (T_ - 1);
        }
        return;
    }

    // Pass 2b: sparse gather
    float acc0 = 0.f, acc1 = 0.f, acc2 = 0.f, acc3 = 0.f;
    float acc4 = 0.f, acc5 = 0.f, acc6 = 0.f, acc7 = 0.f;
    float acc8 = 0.f, acc9 = 0.f, accA = 0.f, accB = 0.f;
    float accC = 0.f, accD = 0.f, accE = 0.f, accF = 0.f;
    float psum = 0.f;

#pragma unroll 1
    for (int i = 0; i < 64; i++) {
        float d8 = s8v[i];
        unsigned ball = __ballot_sync(0xffffffffu, d8 > thr);
        while (ball) {
            int src = __ffs(ball) - 1;
            ball &= ball - 1;
            float d8s = __shfl_sync(0xffffffffu, d8, src);
            float p = __expf(d8s - m);     // identical in all lanes
            psum += p;
            int s = i * 32 + src;
            const float4* vp = (const float4*)(Vb + (size_t)s * DOUT) + lane * 4;
            float4 v0 = vp[0];
            float4 v1 = vp[1];
            float4 v2 = vp[2];
            float4 v3 = vp[3];
            acc0 += p * v0.x; acc1 += p * v0.y; acc2 += p * v0.z; acc3 += p * v0.w;
            acc4 += p * v1.x; acc5 += p * v1.y; acc6 += p * v1.z; acc7 += p * v1.w;
            acc8 += p * v2.x; acc9 += p * v2.y; accA += p * v2.z; accB += p * v2.w;
            accC += p * v3.x; accD += p * v3.y; accE += p * v3.z; accF += p * v3.w;
        }
    }

    float inv = 1.f / psum;
    float4* op = (float4*)(Out + (size_t)q * DOUT) + lane * 4;
    op[0] = make_float4(acc0 * inv, acc1 * inv, acc2 * inv, acc3 * inv);
    op[1] = make_float4(acc4 * inv, acc5 * inv, acc6 * inv, acc7 * inv);
    op[2] = make_float4(acc8 * inv, acc9 * inv, accA * inv, accB * inv);
    op[3] = make_float4(accC * inv, accD * inv, accE * inv, accF * inv);
}

// ---------------------------------------------------------------------------
// Dense attention for queued queries: exact softmax over all 2048 keys.
// Grid = B_ * DSLOT CTAs of 256 threads, DGRP=16 queries per group so every
// V row read is shared by 16 queries. P tile stored TRANSPOSED p_s[kk][j]
// (row stride 20 floats = 80B, 16B-aligned) so the V phase loads all 16 p's
// with 4x LDS.128 then does 32 FFMA per kk — FFMA-dominant mix.
// ---------------------------------------------------------------------------
__global__ __launch_bounds__(256) void attn_dense_kernel(float* __restrict__ Out) {
    __shared__ float p_s[32][20];      // [key-in-chunk][query j], padded
    __shared__ float psum_s[DGRP];
    __shared__ int   qq_s[DGRP];

    int b    = blockIdx.x / DSLOT;
    int slot = blockIdx.x % DSLOT;
    int tid  = threadIdx.x;
    int warp = tid >> 5;
    int lane = tid & 31;

    int count = g_dcount[b];
    const float*  Kb  = g_K + (size_t)b * T_ * DA;
    const float2* Vb2 = (const float2*)(g_V + (size_t)b * T_ * DOUT);

    for (int g = slot; g * DGRP < count; g += DSLOT) {
        int ng = count - g * DGRP;
        if (ng > DGRP) ng = DGRP;

        if (tid < DGRP)
            qq_s[tid] = (tid < ng) ? g_dq[b * T_ + g * DGRP + tid] : 0;
        __syncthreads();

        // P-warp state: queries 2w, 2w+1 (lane = key within chunk)
        int q0i = 2 * warp;
        int q1i = 2 * warp + 1;
        bool v0 = q0i < ng;
        bool v1 = q1i < ng;
        int gq0 = b * T_ + qq_s[v0 ? q0i : 0];
        int gq1 = b * T_ + qq_s[v1 ? q1i : 0];
        float qv0[8], qv1[8];
#pragma unroll
        for (int f = 0; f < 8; f++) {
            qv0[f] = g_Q[(size_t)gq0 * DA + f];
            qv1[f] = g_Q[(size_t)gq1 * DA + f];
        }
        float m0 = g_m[gq0];
        float m1 = g_m[gq1];
        float ps0 = 0.f, ps1 = 0.f;

        float2 acc[DGRP];
#pragma unroll
        for (int j = 0; j < DGRP; j++) acc[j] = make_float2(0.f, 0.f);

        for (int c = 0; c < T_ / 32; c++) {
            int k = c * 32 + lane;
            const float4* kp = (const float4*)(Kb + (size_t)k * DA);
            float4 k0 = kp[0];
            float4 k1 = kp[1];
            float d0 = qv0[0]*k0.x + qv0[1]*k0.y + qv0[2]*k0.z + qv0[3]*k0.w
                     + qv0[4]*k1.x + qv0[5]*k1.y + qv0[6]*k1.z + qv0[7]*k1.w;
            float d1 = qv1[0]*k0.x + qv1[1]*k0.y + qv1[2]*k0.z + qv1[3]*k0.w
                     + qv1[4]*k1.x + qv1[5]*k1.y + qv1[6]*k1.z + qv1[7]*k1.w;
            float e0 = d0 * d0; e0 = e0 * e0; e0 = e0 * e0;
            float e1 = d1 * d1; e1 = e1 * e1; e1 = e1 * e1;
            float p0 = v0 ? __expf(e0 - m0) : 0.f;
            float p1 = v1 ? __expf(e1 - m1) : 0.f;
            ps0 += p0;
            ps1 += p1;
            p_s[lane][q0i] = p0;
            p_s[lane][q1i] = p1;
            __syncthreads();

            // V phase: warp w owns columns [64w, 64w+64); lane -> 2 cols
            const float2* vcol = Vb2 + (size_t)(c * 32) * 256 + warp * 32 + lane;
#pragma unroll 4
            for (int kk = 0; kk < 32; kk++) {
                float2 v = vcol[(size_t)kk * 256];
                float pr[16];
                *(float4*)(pr)      = *(const float4*)(&p_s[kk][0]);
                *(float4*)(pr + 4)  = *(const float4*)(&p_s[kk][4]);
                *(float4*)(pr + 8)  = *(const float4*)(&p_s[kk][8]);
                *(float4*)(pr + 12) = *(const float4*)(&p_s[kk][12]);
#pragma unroll
                for (int j = 0; j < DGRP; j++) {
                    acc[j].x += pr[j] * v.x;
                    acc[j].y += pr[j] * v.y;
                }
            }
            __syncthreads();
        }

        // psum reduce and publish
#pragma unroll
        for (int off = 16; off >= 1; off >>= 1) {
            ps0 += __shfl_xor_sync(0xffffffffu, ps0, off);
            ps1 += __shfl_xor_sync(0xffffffffu, ps1, off);
        }
        if (lane == 0) {
            if (v0) psum_s[q0i] = ps0;
            if (v1) psum_s[q1i] = ps1;
        }
        __syncthreads();

        for (int j = 0; j < ng; j++) {
            float inv = 1.f / psum_s[j];
            int gq = b * T_ + qq_s[j];
            float2* op = (float2*)(Out + (size_t)gq * DOUT) + warp * 32 + lane;
            *op = make_float2(acc[j].x * inv, acc[j].y * inv);
        }
        __syncthreads();
    }
}

// ---------------------------------------------------------------------------
extern "C" void kernel_launch(void* const* d_in, const int* in_sizes, int n_in,
                              void* d_out, int out_size) {
    (void)in_sizes; (void)n_in; (void)out_size;
    const float* X  = (const float*)d_in[0];
    const float* Wq = (const float*)d_in[1];
    const float* Wk = (const float*)d_in[2];
    const float* Wv = (const float*)d_in[3];
    float* Out = (float*)d_out;

    vproj_kernel<<<dim3(DOUT / 128, (B_ * T_) / 128), 256>>>(X, Wv);
    zero_kernel<<<1, 32>>>();
    qk_kernel<<<(B_ * T_) / 32, 256>>>(X, Wq, Wk);
    attn_sparse_kernel<<<(B_ * T_) / 8, 256>>>(Out);
    attn_dense_kernel<<<B_ * DSLOT, 256>>>(Out);
}

// round 7
// speedup vs baseline: 4.3045x; 1.3297x over previous
#include <cuda_runtime.h>
#include <math.h>

#define B_    8
#define T_    2048
#define DIN   512
#define DA    8
#define DOUT  512
#define NCAP  384         // survivor cap for the sparse gather path
#define THR   16.0f       // exp(-16) ~ 1.1e-7; dropped mass <= 2048e-16 ~ 2.3e-4
#define DGRP  16          // dense queries per group
#define DSLOT 64          // dense work-unit slots per batch (group x col-quarter)

__device__ __align__(16) float g_Q[B_ * T_ * DA];
__device__ __align__(16) float g_K[B_ * T_ * DA];
__device__ __align__(16) float g_V[B_ * T_ * DOUT];
__device__ float g_m[B_ * T_];          // per-query max of d^8
__device__ int   g_dcount[B_];          // dense-queue counts
__device__ int   g_dq[B_ * T_];         // dense-queue (local q indices per batch)

// ---------------------------------------------------------------------------
__global__ void zero_kernel() {
    if (threadIdx.x < B_) g_dcount[threadIdx.x] = 0;
}

// ---------------------------------------------------------------------------
// V = X @ Wv. fp32 SGEMM, measured 215us. Unchanged.
// ---------------------------------------------------------------------------
__global__ __launch_bounds__(256, 2) void vproj_kernel(const float* __restrict__ A,
                                                       const float* __restrict__ Bw) {
    __shared__ float As[16][132];
    __shared__ float Bs[16][128];

    int t  = threadIdx.x;
    int bm = blockIdx.y;
    int bn = blockIdx.x;
    int tr = t >> 4;
    int tc = t & 15;

    const float* Ag = A + (size_t)bm * 128 * DIN;
    const float* Bg = Bw + (size_t)bn * 128;

    float acc[8][8];
#pragma unroll
    for (int i = 0; i < 8; i++)
#pragma unroll
        for (int j = 0; j < 8; j++) acc[i][j] = 0.f;

    for (int kt = 0; kt < DIN; kt += 16) {
#pragma unroll
        for (int e = t; e < 512; e += 256) {
            int row = e >> 2;
            int cg  = (e & 3) << 2;
            float4 v = *(const float4*)(Ag + (size_t)row * DIN + kt + cg);
            As[cg + 0][row] = v.x;
            As[cg + 1][row] = v.y;
            As[cg + 2][row] = v.z;
            As[cg + 3][row] = v.w;
        }
#pragma unroll
        for (int e = t; e < 512; e += 256) {
            int row = e >> 5;
            int cg  = (e & 31) << 2;
            *(float4*)(&Bs[row][cg]) =
                *(const float4*)(Bg + (size_t)(kt + row) * DOUT + cg);
        }
        __syncthreads();

#pragma unroll
        for (int k = 0; k < 16; k++) {
            float a0[8], b0[8];
            *(float4*)(a0)     = *(const float4*)(&As[k][tr * 4]);
            *(float4*)(a0 + 4) = *(const float4*)(&As[k][tr * 4 + 64]);
            *(float4*)(b0)     = *(const float4*)(&Bs[k][tc * 4]);
            *(float4*)(b0 + 4) = *(const float4*)(&Bs[k][tc * 4 + 64]);
#pragma unroll
            for (int i = 0; i < 8; i++)
#pragma unroll
                for (int j = 0; j < 8; j++)
                    acc[i][j] += a0[i] * b0[j];
        }
        __syncthreads();
    }

#pragma unroll
    for (int i = 0; i < 8; i++) {
        int rr = tr * 4 + ((i & 4) ? 64 : 0) + (i & 3);
        float* cp = g_V + (size_t)(bm * 128 + rr) * DOUT + bn * 128;
        *(float4*)(cp + tc * 4)      = make_float4(acc[i][0], acc[i][1], acc[i][2], acc[i][3]);
        *(float4*)(cp + tc * 4 + 64) = make_float4(acc[i][4], acc[i][5], acc[i][6], acc[i][7]);
    }
}

// ---------------------------------------------------------------------------
// Q,K projections (measured ~35us). Unchanged.
// ---------------------------------------------------------------------------
__global__ __launch_bounds__(256) void qk_kernel(const float* __restrict__ X,
                                                 const float* __restrict__ Wq,
                                                 const float* __restrict__ Wk) {
    int warp = threadIdx.x >> 5;
    int lane = threadIdx.x & 31;
    int tok0 = blockIdx.x * 32 + warp * 4;

    float aq[4][8], ak[4][8];
#pragma unroll
    for (int t = 0; t < 4; t++)
#pragma unroll
        for (int f = 0; f < 8; f++) { aq[t][f] = 0.f; ak[t][f] = 0.f; }

#pragma unroll 4
    for (int d = lane; d < DIN; d += 32) {
        float xv[4];
#pragma unroll
        for (int t = 0; t < 4; t++) xv[t] = X[(size_t)(tok0 + t) * DIN + d];
        float4 q0 = *(const float4*)(Wq + (size_t)d * 8);
        float4 q1 = *(const float4*)(Wq + (size_t)d * 8 + 4);
        float4 k0 = *(const float4*)(Wk + (size_t)d * 8);
        float4 k1 = *(const float4*)(Wk + (size_t)d * 8 + 4);
#pragma unroll
        for (int t = 0; t < 4; t++) {
            aq[t][0] += xv[t] * q0.x; aq[t][1] += xv[t] * q0.y;
            aq[t][2] += xv[t] * q0.z; aq[t][3] += xv[t] * q0.w;
            aq[t][4] += xv[t] * q1.x; aq[t][5] += xv[t] * q1.y;
            aq[t][6] += xv[t] * q1.z; aq[t][7] += xv[t] * q1.w;
            ak[t][0] += xv[t] * k0.x; ak[t][1] += xv[t] * k0.y;
            ak[t][2] += xv[t] * k0.z; ak[t][3] += xv[t] * k0.w;
            ak[t][4] += xv[t] * k1.x; ak[t][5] += xv[t] * k1.y;
            ak[t][6] += xv[t] * k1.z; ak[t][7] += xv[t] * k1.w;
        }
    }

#pragma unroll
    for (int t = 0; t < 4; t++) {
#pragma unroll
        for (int f = 0; f < 8; f++) {
#pragma unroll
            for (int off = 16; off >= 1; off >>= 1) {
                aq[t][f] += __shfl_xor_sync(0xffffffffu, aq[t][f], off);
                ak[t][f] += __shfl_xor_sync(0xffffffffu, ak[t][f], off);
            }
        }
        if (lane == 0) {
            float* qo = g_Q + (size_t)(tok0 + t) * 8;
            float* ko = g_K + (size_t)(tok0 + t) * 8;
            *(float4*)(qo)     = make_float4(aq[t][0], aq[t][1], aq[t][2], aq[t][3]);
            *(float4*)(qo + 4) = make_float4(aq[t][4], aq[t][5], aq[t][6], aq[t][7]);
            *(float4*)(ko)     = make_float4(ak[t][0], ak[t][1], ak[t][2], ak[t][3]);
            *(float4*)(ko + 4) = make_float4(ak[t][4], ak[t][5], ak[t][6], ak[t][7]);
        }
    }
}

// ---------------------------------------------------------------------------
// Sparse attention (one query per warp). Pass 1: scan, m. Pass 2a: count
// survivors n (keys with p > e^-THR). If n <= NCAP: ballot-walk gather.
// Else enqueue for dense kernel.
// ---------------------------------------------------------------------------
__global__ __launch_bounds__(256) void attn_sparse_kernel(float* __restrict__ Out) {
    int warp = threadIdx.x >> 5;
    int lane = threadIdx.x & 31;
    int q    = blockIdx.x * 8 + warp;
    int b    = q >> 11;
    const float* Kb = g_K + (size_t)b * T_ * DA;
    const float* Vb = g_V + (size_t)b * T_ * DOUT;

    float4 qa = *(const float4*)(g_Q + (size_t)q * DA);
    float4 qb = *(const float4*)(g_Q + (size_t)q * DA + 4);

    float s8v[64];
    float m = -INFINITY;

#pragma unroll 1
    for (int i = 0; i < 64; i++) {
        int s = i * 32 + lane;
        const float4* kp = (const float4*)(Kb + (size_t)s * DA);
        float4 k0 = kp[0];
        float4 k1 = kp[1];
        float d = qa.x * k0.x + qa.y * k0.y + qa.z * k0.z + qa.w * k0.w
                + qb.x * k1.x + qb.y * k1.y + qb.z * k1.z + qb.w * k1.w;
        float d2 = d * d;
        float d4 = d2 * d2;
        float d8 = d4 * d4;
        s8v[i] = d8;
        m = fmaxf(m, d8);
    }
#pragma unroll
    for (int off = 16; off >= 1; off >>= 1)
        m = fmaxf(m, __shfl_xor_sync(0xffffffffu, m, off));

    if (lane == 0) g_m[q] = m;

    float thr = m - THR;

    // Pass 2a: survivor count
    int n = 0;
#pragma unroll 1
    for (int i = 0; i < 64; i++)
        n += __popc(__ballot_sync(0xffffffffu, s8v[i] > thr));

    if (n > NCAP) {
        if (lane == 0) {
            int idx = atomicAdd(&g_dcount[b], 1);
            g_dq[b * T_ + idx] = q & (T_ - 1);
        }
        return;
    }

    // Pass 2b: sparse gather
    float acc0 = 0.f, acc1 = 0.f, acc2 = 0.f, acc3 = 0.f;
    float acc4 = 0.f, acc5 = 0.f, acc6 = 0.f, acc7 = 0.f;
    float acc8 = 0.f, acc9 = 0.f, accA = 0.f, accB = 0.f;
    float accC = 0.f, accD = 0.f, accE = 0.f, accF = 0.f;
    float psum = 0.f;

#pragma unroll 1
    for (int i = 0; i < 64; i++) {
        float d8 = s8v[i];
        unsigned ball = __ballot_sync(0xffffffffu, d8 > thr);
        while (ball) {
            int src = __ffs(ball) - 1;
            ball &= ball - 1;
            float d8s = __shfl_sync(0xffffffffu, d8, src);
            float p = __expf(d8s - m);     // identical in all lanes
            psum += p;
            int s = i * 32 + src;
            const float4* vp = (const float4*)(Vb + (size_t)s * DOUT) + lane * 4;
            float4 v0 = vp[0];
            float4 v1 = vp[1];
            float4 v2 = vp[2];
            float4 v3 = vp[3];
            acc0 += p * v0.x; acc1 += p * v0.y; acc2 += p * v0.z; acc3 += p * v0.w;
            acc4 += p * v1.x; acc5 += p * v1.y; acc6 += p * v1.z; acc7 += p * v1.w;
            acc8 += p * v2.x; acc9 += p * v2.y; accA += p * v2.z; accB += p * v2.w;
            accC += p * v3.x; accD += p * v3.y; accE += p * v3.z; accF += p * v3.w;
        }
    }

    float inv = 1.f / psum;
    float4* op = (float4*)(Out + (size_t)q * DOUT) + lane * 4;
    op[0] = make_float4(acc0 * inv, acc1 * inv, acc2 * inv, acc3 * inv);
    op[1] = make_float4(acc4 * inv, acc5 * inv, acc6 * inv, acc7 * inv);
    op[2] = make_float4(acc8 * inv, acc9 * inv, accA * inv, accB * inv);
    op[3] = make_float4(accC * inv, accD * inv, accE * inv, accF * inv);
}

// ---------------------------------------------------------------------------
// Dense attention (exact softmax over all 2048 keys) for queued queries.
// Work unit = (group of DGRP=16 queries, 128-column quarter): 4x CTA
// parallelism vs one-CTA-per-group. Grid = B_ * DSLOT.
// P phase: warp w computes p for queries 2w,2w+1 into p_s[key][query].
// V phase: each thread owns ONE column (col = cq*128 + warp*16 + lane%16);
// half-warps split the 32 keys (even/odd), combined by shfl_xor(16) at end.
// ---------------------------------------------------------------------------
__global__ __launch_bounds__(256) void attn_dense_kernel(float* __restrict__ Out) {
    __shared__ float p_s[32][20];      // [key-in-chunk][query j], padded
    __shared__ float psum_s[DGRP];
    __shared__ int   qq_s[DGRP];

    int b    = blockIdx.x / DSLOT;
    int slot = blockIdx.x % DSLOT;
    int tid  = threadIdx.x;
    int warp = tid >> 5;
    int lane = tid & 31;

    int count = g_dcount[b];
    const float* Kb = g_K + (size_t)b * T_ * DA;
    const float* Vb = g_V + (size_t)b * T_ * DOUT;

    for (int u = slot; (u >> 2) * DGRP < count; u += DSLOT) {
        int g  = u >> 2;           // group
        int cq = u & 3;            // column quarter
        int ng = count - g * DGRP;
        if (ng > DGRP) ng = DGRP;

        if (tid < DGRP)
            qq_s[tid] = (tid < ng) ? g_dq[b * T_ + g * DGRP + tid] : 0;
        __syncthreads();

        // P-warp state: queries 2w, 2w+1 (lane = key within chunk)
        int q0i = 2 * warp;
        int q1i = 2 * warp + 1;
        bool v0 = q0i < ng;
        bool v1 = q1i < ng;
        int gq0 = b * T_ + qq_s[v0 ? q0i : 0];
        int gq1 = b * T_ + qq_s[v1 ? q1i : 0];
        float qv0[8], qv1[8];
#pragma unroll
        for (int f = 0; f < 8; f++) {
            qv0[f] = g_Q[(size_t)gq0 * DA + f];
            qv1[f] = g_Q[(size_t)gq1 * DA + f];
        }
        float m0 = g_m[gq0];
        float m1 = g_m[gq1];
        float ps0 = 0.f, ps1 = 0.f;

        // V-phase ownership
        int col  = cq * 128 + warp * 16 + (lane & 15);
        int kpar = lane >> 4;      // half-warp key parity
        float acc[DGRP];
#pragma unroll
        for (int j = 0; j < DGRP; j++) acc[j] = 0.f;

        for (int c = 0; c < T_ / 32; c++) {
            // --- P phase ---
            int k = c * 32 + lane;
            const float4* kp = (const float4*)(Kb + (size_t)k * DA);
            float4 k0 = kp[0];
            float4 k1 = kp[1];
            float d0 = qv0[0]*k0.x + qv0[1]*k0.y + qv0[2]*k0.z + qv0[3]*k0.w
                     + qv0[4]*k1.x + qv0[5]*k1.y + qv0[6]*k1.z + qv0[7]*k1.w;
            float d1 = qv1[0]*k0.x + qv1[1]*k0.y + qv1[2]*k0.z + qv1[3]*k0.w
                     + qv1[4]*k1.x + qv1[5]*k1.y + qv1[6]*k1.z + qv1[7]*k1.w;
            float e0 = d0 * d0; e0 = e0 * e0; e0 = e0 * e0;
            float e1 = d1 * d1; e1 = e1 * e1; e1 = e1 * e1;
            float p0 = v0 ? __expf(e0 - m0) : 0.f;
            float p1 = v1 ? __expf(e1 - m1) : 0.f;
            ps0 += p0;
            ps1 += p1;
            p_s[lane][q0i] = p0;
            p_s[lane][q1i] = p1;
            __syncthreads();

            // --- V phase: one column, 16 keys (this half-warp's parity) ---
            const float* vptr = Vb + (size_t)(c * 32 + kpar) * DOUT + col;
#pragma unroll
            for (int kk2 = 0; kk2 < 16; kk2++) {
                int kk = 2 * kk2 + kpar;
                float v = vptr[(size_t)(2 * kk2) * DOUT];
                float pr[16];
                *(float4*)(pr)      = *(const float4*)(&p_s[kk][0]);
                *(float4*)(pr + 4)  = *(const float4*)(&p_s[kk][4]);
                *(float4*)(pr + 8)  = *(const float4*)(&p_s[kk][8]);
                *(float4*)(pr + 12) = *(const float4*)(&p_s[kk][12]);
#pragma unroll
                for (int j = 0; j < DGRP; j++)
                    acc[j] += pr[j] * v;
            }
            __syncthreads();
        }

        // psum reduce and publish
#pragma unroll
        for (int off = 16; off >= 1; off >>= 1) {
            ps0 += __shfl_xor_sync(0xffffffffu, ps0, off);
            ps1 += __shfl_xor_sync(0xffffffffu, ps1, off);
        }
        if (lane == 0) {
            if (v0) psum_s[q0i] = ps0;
            if (v1) psum_s[q1i] = ps1;
        }
        __syncthreads();

        // combine half-warp partial sums (same col, disjoint keys)
#pragma unroll
        for (int j = 0; j < DGRP; j++)
            acc[j] += __shfl_xor_sync(0xffffffffu, acc[j], 16);

        if (kpar == 0) {
            for (int j = 0; j < ng; j++) {
                int gq = b * T_ + qq_s[j];
                Out[(size_t)gq * DOUT + col] = acc[j] / psum_s[j];
            }
        }
        __syncthreads();
    }
}

// ---------------------------------------------------------------------------
extern "C" void kernel_launch(void* const* d_in, const int* in_sizes, int n_in,
                              void* d_out, int out_size) {
    (void)in_sizes; (void)n_in; (void)out_size;
    const float* X  = (const float*)d_in[0];
    const float* Wq = (const float*)d_in[1];
    const float* Wk = (const float*)d_in[2];
    const float* Wv = (const float*)d_in[3];
    float* Out = (float*)d_out;

    vproj_kernel<<<dim3(DOUT / 128, (B_ * T_) / 128), 256>>>(X, Wv);
    zero_kernel<<<1, 32>>>();
    qk_kernel<<<(B_ * T_) / 32, 256>>>(X, Wq, Wk);
    attn_sparse_kernel<<<(B_ * T_) / 8, 256>>>(Out);
    attn_dense_kernel<<<B_ * DSLOT, 256>>>(Out);
}

// round 8
// speedup vs baseline: 4.5453x; 1.0560x over previous
#include <cuda_runtime.h>
#include <math.h>

#define B_    8
#define T_    2048
#define DIN   512
#define DA    8
#define DOUT  512
#define NCAP  384         // survivor cap for the sparse gather path
#define THR   16.0f       // exp(-16) ~ 1.1e-7 dropped-per-key bound
#define DGRP  16          // dense queries per group
#define NSPLIT 4          // column quarters per group
#define DGRID 512         // persistent dense CTAs

__device__ __align__(16) float g_Q[B_ * T_ * DA];
__device__ __align__(16) float g_K[B_ * T_ * DA];
__device__ __align__(16) float g_V[B_ * T_ * DOUT];
__device__ float g_m[B_ * T_];          // per-query max of d^8
__device__ int   g_dcount[B_];          // dense-queue counts
__device__ int   g_dq[B_ * T_];         // dense-queue (local q indices per batch)
__device__ int   g_units[B_ * (T_ / DGRP) * NSPLIT + 64];
__device__ int   g_nunits;
__device__ int   g_ticket;

// ---------------------------------------------------------------------------
__global__ void zero_kernel() {
    if (threadIdx.x < B_) g_dcount[threadIdx.x] = 0;
}

// Build the flat dense work queue: one unit = (batch, group, col quarter).
__global__ void plan_kernel() {
    if (threadIdx.x != 0) return;
    int total = 0;
    for (int b = 0; b < B_; b++) {
        int cnt = g_dcount[b];
        int groups = (cnt + DGRP - 1) / DGRP;
        for (int g = 0; g < groups; g++)
            for (int cq = 0; cq < NSPLIT; cq++)
                g_units[total++] = (b << 16) | (g << 4) | cq;
    }
    g_nunits = total;
    g_ticket = 0;
}

// ---------------------------------------------------------------------------
// V = X @ Wv. fp32 SGEMM, measured 215us. Unchanged.
// ---------------------------------------------------------------------------
__global__ __launch_bounds__(256, 2) void vproj_kernel(const float* __restrict__ A,
                                                       const float* __restrict__ Bw) {
    __shared__ float As[16][132];
    __shared__ float Bs[16][128];

    int t  = threadIdx.x;
    int bm = blockIdx.y;
    int bn = blockIdx.x;
    int tr = t >> 4;
    int tc = t & 15;

    const float* Ag = A + (size_t)bm * 128 * DIN;
    const float* Bg = Bw + (size_t)bn * 128;

    float acc[8][8];
#pragma unroll
    for (int i = 0; i < 8; i++)
#pragma unroll
        for (int j = 0; j < 8; j++) acc[i][j] = 0.f;

    for (int kt = 0; kt < DIN; kt += 16) {
#pragma unroll
        for (int e = t; e < 512; e += 256) {
            int row = e >> 2;
            int cg  = (e & 3) << 2;
            float4 v = *(const float4*)(Ag + (size_t)row * DIN + kt + cg);
            As[cg + 0][row] = v.x;
            As[cg + 1][row] = v.y;
            As[cg + 2][row] = v.z;
            As[cg + 3][row] = v.w;
        }
#pragma unroll
        for (int e = t; e < 512; e += 256) {
            int row = e >> 5;
            int cg  = (e & 31) << 2;
            *(float4*)(&Bs[row][cg]) =
                *(const float4*)(Bg + (size_t)(kt + row) * DOUT + cg);
        }
        __syncthreads();

#pragma unroll
        for (int k = 0; k < 16; k++) {
            float a0[8], b0[8];
            *(float4*)(a0)     = *(const float4*)(&As[k][tr * 4]);
            *(float4*)(a0 + 4) = *(const float4*)(&As[k][tr * 4 + 64]);
            *(float4*)(b0)     = *(const float4*)(&Bs[k][tc * 4]);
            *(float4*)(b0 + 4) = *(const float4*)(&Bs[k][tc * 4 + 64]);
#pragma unroll
            for (int i = 0; i < 8; i++)
#pragma unroll
                for (int j = 0; j < 8; j++)
                    acc[i][j] += a0[i] * b0[j];
        }
        __syncthreads();
    }

#pragma unroll
    for (int i = 0; i < 8; i++) {
        int rr = tr * 4 + ((i & 4) ? 64 : 0) + (i & 3);
        float* cp = g_V + (size_t)(bm * 128 + rr) * DOUT + bn * 128;
        *(float4*)(cp + tc * 4)      = make_float4(acc[i][0], acc[i][1], acc[i][2], acc[i][3]);
        *(float4*)(cp + tc * 4 + 64) = make_float4(acc[i][4], acc[i][5], acc[i][6], acc[i][7]);
    }
}

// ---------------------------------------------------------------------------
// Q,K projections (measured ~35us). Unchanged.
// ---------------------------------------------------------------------------
__global__ __launch_bounds__(256) void qk_kernel(const float* __restrict__ X,
                                                 const float* __restrict__ Wq,
                                                 const float* __restrict__ Wk) {
    int warp = threadIdx.x >> 5;
    int lane = threadIdx.x & 31;
    int tok0 = blockIdx.x * 32 + warp * 4;

    float aq[4][8], ak[4][8];
#pragma unroll
    for (int t = 0; t < 4; t++)
#pragma unroll
        for (int f = 0; f < 8; f++) { aq[t][f] = 0.f; ak[t][f] = 0.f; }

#pragma unroll 4
    for (int d = lane; d < DIN; d += 32) {
        float xv[4];
#pragma unroll
        for (int t = 0; t < 4; t++) xv[t] = X[(size_t)(tok0 + t) * DIN + d];
        float4 q0 = *(const float4*)(Wq + (size_t)d * 8);
        float4 q1 = *(const float4*)(Wq + (size_t)d * 8 + 4);
        float4 k0 = *(const float4*)(Wk + (size_t)d * 8);
        float4 k1 = *(const float4*)(Wk + (size_t)d * 8 + 4);
#pragma unroll
        for (int t = 0; t < 4; t++) {
            aq[t][0] += xv[t] * q0.x; aq[t][1] += xv[t] * q0.y;
            aq[t][2] += xv[t] * q0.z; aq[t][3] += xv[t] * q0.w;
            aq[t][4] += xv[t] * q1.x; aq[t][5] += xv[t] * q1.y;
            aq[t][6] += xv[t] * q1.z; aq[t][7] += xv[t] * q1.w;
            ak[t][0] += xv[t] * k0.x; ak[t][1] += xv[t] * k0.y;
            ak[t][2] += xv[t] * k0.z; ak[t][3] += xv[t] * k0.w;
            ak[t][4] += xv[t] * k1.x; ak[t][5] += xv[t] * k1.y;
            ak[t][6] += xv[t] * k1.z; ak[t][7] += xv[t] * k1.w;
        }
    }

#pragma unroll
    for (int t = 0; t < 4; t++) {
#pragma unroll
        for (int f = 0; f < 8; f++) {
#pragma unroll
            for (int off = 16; off >= 1; off >>= 1) {
                aq[t][f] += __shfl_xor_sync(0xffffffffu, aq[t][f], off);
                ak[t][f] += __shfl_xor_sync(0xffffffffu, ak[t][f], off);
            }
        }
        if (lane == 0) {
            float* qo = g_Q + (size_t)(tok0 + t) * 8;
            float* ko = g_K + (size_t)(tok0 + t) * 8;
            *(float4*)(qo)     = make_float4(aq[t][0], aq[t][1], aq[t][2], aq[t][3]);
            *(float4*)(qo + 4) = make_float4(aq[t][4], aq[t][5], aq[t][6], aq[t][7]);
            *(float4*)(ko)     = make_float4(ak[t][0], ak[t][1], ak[t][2], ak[t][3]);
            *(float4*)(ko + 4) = make_float4(ak[t][4], ak[t][5], ak[t][6], ak[t][7]);
        }
    }
}

// ---------------------------------------------------------------------------
// Sparse attention. Pass 1 unrolled x2 (4 LDG.128 in flight) to cut the
// exposed-latency serialization seen in ncu (issue 24%, nothing saturated).
// ---------------------------------------------------------------------------
__global__ __launch_bounds__(256) void attn_sparse_kernel(float* __restrict__ Out) {
    int warp = threadIdx.x >> 5;
    int lane = threadIdx.x & 31;
    int q    = blockIdx.x * 8 + warp;
    int b    = q >> 11;
    const float* Kb = g_K + (size_t)b * T_ * DA;
    const float* Vb = g_V + (size_t)b * T_ * DOUT;

    float4 qa = *(const float4*)(g_Q + (size_t)q * DA);
    float4 qb = *(const float4*)(g_Q + (size_t)q * DA + 4);

    float s8v[64];
    float m = -INFINITY;

#pragma unroll 1
    for (int i = 0; i < 64; i += 2) {
        int s0 = i * 32 + lane;
        const float4* kp0 = (const float4*)(Kb + (size_t)s0 * DA);
        const float4* kp1 = (const float4*)(Kb + (size_t)(s0 + 32) * DA);
        float4 a0 = kp0[0];
        float4 a1 = kp0[1];
        float4 b0 = kp1[0];
        float4 b1 = kp1[1];
        float da = qa.x * a0.x + qa.y * a0.y + qa.z * a0.z + qa.w * a0.w
                 + qb.x * a1.x + qb.y * a1.y + qb.z * a1.z + qb.w * a1.w;
        float db = qa.x * b0.x + qa.y * b0.y + qa.z * b0.z + qa.w * b0.w
                 + qb.x * b1.x + qb.y * b1.y + qb.z * b1.z + qb.w * b1.w;
        float da2 = da * da, da4 = da2 * da2, da8 = da4 * da4;
        float db2 = db * db, db4 = db2 * db2, db8 = db4 * db4;
        s8v[i]     = da8;
        s8v[i + 1] = db8;
        m = fmaxf(m, fmaxf(da8, db8));
    }
#pragma unroll
    for (int off = 16; off >= 1; off >>= 1)
        m = fmaxf(m, __shfl_xor_sync(0xffffffffu, m, off));

    if (lane == 0) g_m[q] = m;

    float thr = m - THR;

    // survivor count
    int n = 0;
#pragma unroll 1
    for (int i = 0; i < 64; i++)
        n += __popc(__ballot_sync(0xffffffffu, s8v[i] > thr));

    if (n > NCAP) {
        if (lane == 0) {
            int idx = atomicAdd(&g_dcount[b], 1);
            g_dq[b * T_ + idx] = q & (T_ - 1);
        }
        return;
    }

    // sparse gather
    float acc0 = 0.f, acc1 = 0.f, acc2 = 0.f, acc3 = 0.f;
    float acc4 = 0.f, acc5 = 0.f, acc6 = 0.f, acc7 = 0.f;
    float acc8 = 0.f, acc9 = 0.f, accA = 0.f, accB = 0.f;
    float accC = 0.f, accD = 0.f, accE = 0.f, accF = 0.f;
    float psum = 0.f;

#pragma unroll 1
    for (int i = 0; i < 64; i++) {
        float d8 = s8v[i];
        unsigned ball = __ballot_sync(0xffffffffu, d8 > thr);
        while (ball) {
            int src = __ffs(ball) - 1;
            ball &= ball - 1;
            float d8s = __shfl_sync(0xffffffffu, d8, src);
            float p = __expf(d8s - m);     // identical in all lanes
            psum += p;
            int s = i * 32 + src;
            const float4* vp = (const float4*)(Vb + (size_t)s * DOUT) + lane * 4;
            float4 v0 = vp[0];
            float4 v1 = vp[1];
            float4 v2 = vp[2];
            float4 v3 = vp[3];
            acc0 += p * v0.x; acc1 += p * v0.y; acc2 += p * v0.z; acc3 += p * v0.w;
            acc4 += p * v1.x; acc5 += p * v1.y; acc6 += p * v1.z; acc7 += p * v1.w;
            acc8 += p * v2.x; acc9 += p * v2.y; accA += p * v2.z; accB += p * v2.w;
            accC += p * v3.x; accD += p * v3.y; accE += p * v3.z; accF += p * v3.w;
        }
    }

    float inv = 1.f / psum;
    float4* op = (float4*)(Out + (size_t)q * DOUT) + lane * 4;
    op[0] = make_float4(acc0 * inv, acc1 * inv, acc2 * inv, acc3 * inv);
    op[1] = make_float4(acc4 * inv, acc5 * inv, acc6 * inv, acc7 * inv);
    op[2] = make_float4(acc8 * inv, acc9 * inv, accA * inv, accB * inv);
    op[3] = make_float4(accC * inv, accD * inv, accE * inv, accF * inv);
}

// ---------------------------------------------------------------------------
// Dense attention: persistent CTAs pull (batch, group, col-quarter) units
// from a flat global ticket queue — perfect load balance. Each unit writes
// a disjoint output region, so output is deterministic regardless of
// CTA<->unit assignment. Body identical to R7's proven version.
// ---------------------------------------------------------------------------
__global__ __launch_bounds__(256) void attn_dense_kernel(float* __restrict__ Out) {
    __shared__ float p_s[32][20];
    __shared__ float psum_s[DGRP];
    __shared__ int   qq_s[DGRP];
    __shared__ int   s_unit;

    int tid  = threadIdx.x;
    int warp = tid >> 5;
    int lane = tid & 31;

    while (true) {
        if (tid == 0) s_unit = atomicAdd(&g_ticket, 1);
        __syncthreads();
        int u = s_unit;
        if (u >= g_nunits) return;
        int enc = g_units[u];
        int b   = enc >> 16;
        int g   = (enc >> 4) & 0xFFF;
        int cq  = enc & 0xF;
        __syncthreads();

        int count = g_dcount[b];
        const float* Kb = g_K + (size_t)b * T_ * DA;
        const float* Vb = g_V + (size_t)b * T_ * DOUT;

        int ng = count - g * DGRP;
        if (ng > DGRP) ng = DGRP;

        if (tid < DGRP)
            qq_s[tid] = (tid < ng) ? g_dq[b * T_ + g * DGRP + tid] : 0;
        __syncthreads();

        int q0i = 2 * warp;
        int q1i = 2 * warp + 1;
        bool v0 = q0i < ng;
        bool v1 = q1i < ng;
        int gq0 = b * T_ + qq_s[v0 ? q0i : 0];
        int gq1 = b * T_ + qq_s[v1 ? q1i : 0];
        float qv0[8], qv1[8];
#pragma unroll
        for (int f = 0; f < 8; f++) {
            qv0[f] = g_Q[(size_t)gq0 * DA + f];
            qv1[f] = g_Q[(size_t)gq1 * DA + f];
        }
        float m0 = g_m[gq0];
        float m1 = g_m[gq1];
        float ps0 = 0.f, ps1 = 0.f;

        int col  = cq * 128 + warp * 16 + (lane & 15);
        int kpar = lane >> 4;
        float acc[DGRP];
#pragma unroll
        for (int j = 0; j < DGRP; j++) acc[j] = 0.f;

        for (int c = 0; c < T_ / 32; c++) {
            int k = c * 32 + lane;
            const float4* kp = (const float4*)(Kb + (size_t)k * DA);
            float4 k0 = kp[0];
            float4 k1 = kp[1];
            float d0 = qv0[0]*k0.x + qv0[1]*k0.y + qv0[2]*k0.z + qv0[3]*k0.w
                     + qv0[4]*k1.x + qv0[5]*k1.y + qv0[6]*k1.z + qv0[7]*k1.w;
            float d1 = qv1[0]*k0.x + qv1[1]*k0.y + qv1[2]*k0.z + qv1[3]*k0.w
                     + qv1[4]*k1.x + qv1[5]*k1.y + qv1[6]*k1.z + qv1[7]*k1.w;
            float e0 = d0 * d0; e0 = e0 * e0; e0 = e0 * e0;
            float e1 = d1 * d1; e1 = e1 * e1; e1 = e1 * e1;
            float p0 = v0 ? __expf(e0 - m0) : 0.f;
            float p1 = v1 ? __expf(e1 - m1) : 0.f;
            ps0 += p0;
            ps1 += p1;
            p_s[lane][q0i] = p0;
            p_s[lane][q1i] = p1;
            __syncthreads();

            const float* vptr = Vb + (size_t)(c * 32 + kpar) * DOUT + col;
#pragma unroll
            for (int kk2 = 0; kk2 < 16; kk2++) {
                int kk = 2 * kk2 + kpar;
                float v = vptr[(size_t)(2 * kk2) * DOUT];
                float pr[16];
                *(float4*)(pr)      = *(const float4*)(&p_s[kk][0]);
                *(float4*)(pr + 4)  = *(const float4*)(&p_s[kk][4]);
                *(float4*)(pr + 8)  = *(const float4*)(&p_s[kk][8]);
                *(float4*)(pr + 12) = *(const float4*)(&p_s[kk][12]);
#pragma unroll
                for (int j = 0; j < DGRP; j++)
                    acc[j] += pr[j] * v;
            }
            __syncthreads();
        }

#pragma unroll
        for (int off = 16; off >= 1; off >>= 1) {
            ps0 += __shfl_xor_sync(0xffffffffu, ps0, off);
            ps1 += __shfl_xor_sync(0xffffffffu, ps1, off);
        }
        if (lane == 0) {
            if (v0) psum_s[q0i] = ps0;
            if (v1) psum_s[q1i] = ps1;
        }
        __syncthreads();

#pragma unroll
        for (int j = 0; j < DGRP; j++)
            acc[j] += __shfl_xor_sync(0xffffffffu, acc[j], 16);

        if (kpar == 0) {
            for (int j = 0; j < ng; j++) {
                int gq = b * T_ + qq_s[j];
                Out[(size_t)gq * DOUT + col] = acc[j] / psum_s[j];
            }
        }
        __syncthreads();
    }
}

// ---------------------------------------------------------------------------
extern "C" void kernel_launch(void* const* d_in, const int* in_sizes, int n_in,
                              void* d_out, int out_size) {
    (void)in_sizes; (void)n_in; (void)out_size;
    const float* X  = (const float*)d_in[0];
    const float* Wq = (const float*)d_in[1];
    const float* Wk = (const float*)d_in[2];
    const float* Wv = (const float*)d_in[3];
    float* Out = (float*)d_out;

    vproj_kernel<<<dim3(DOUT / 128, (B_ * T_) / 128), 256>>>(X, Wv);
    zero_kernel<<<1, 32>>>();
    qk_kernel<<<(B_ * T_) / 32, 256>>>(X, Wq, Wk);
    attn_sparse_kernel<<<(B_ * T_) / 8, 256>>>(Out);
    plan_kernel<<<1, 32>>>();
    attn_dense_kernel<<<DGRID, 256>>>(Out);
}